// round 15
// baseline (speedup 1.0000x reference)
#include <cuda_runtime.h>
#include <cuda_fp16.h>

#define FULL 0xffffffffu

__device__ __forceinline__ float wsum(float v){
  #pragma unroll
  for (int o = 16; o; o >>= 1) v += __shfl_xor_sync(FULL, v, o);
  return v;
}

// ---- shared memory layout (byte offsets) ----
// WHp: feature-major paired nodes: plane f (0..63) at WHp + 68*f,
//      entry m (0..63) = {WH[2m][f], WH[2m+1][f]}.  68*4B = 272B per plane
//      -> every plane 16B-aligned; LDS.128 conflict-free (stride 68 % 32 == 4).
#define O_WHP  0        // 64 planes x 68 half2                     (17408 B)
#define O_H1   17408    // half 128x64 row-major                    (16384 B)
#define O_Q    33792    // half2 8 warps x 8 rows x 64 pairs        (16384 B)
#define O_W2H  50176    // half2 64x32 : {W2[k][l], W2[k][l+32]}    (8192 B)
#define O_C    58368    // float 128
#define O_S    58880    // float 128
#define O_T    59392    // float 128
#define O_EMB  59904    // float 128x8
#define O_XM   64000    // float 64
#define O_G1   64256    // float 64
#define O_Y    64512    // float 64
#define O_PD   64768    // float 8
#define SMEM_BYTES 64800

__global__ void __launch_bounds__(256, 3)
graphmixer_kernel(const float* __restrict__ gC,   const float* __restrict__ gAdj,
                  const float* __restrict__ gEmb, const float* __restrict__ gW1,
                  const float* __restrict__ gA1,  const float* __restrict__ gW2,
                  const float* __restrict__ gA2,  const float* __restrict__ gLn1g,
                  const float* __restrict__ gLn1b,const float* __restrict__ gLn2g,
                  const float* __restrict__ gLn2b,const float* __restrict__ gHgw,
                  const float* __restrict__ gHgb, const float* __restrict__ gM1w,
                  const float* __restrict__ gM1b, const float* __restrict__ gM2w,
                  const float* __restrict__ gM2b, const float* __restrict__ gHmw,
                  const float* __restrict__ gHmb, const float* __restrict__ gG1w,
                  const float* __restrict__ gG1b, const float* __restrict__ gG2w,
                  const float* __restrict__ gG2b, float* __restrict__ gOut)
{
  extern __shared__ char smraw[];
  __half2* WHp = (__half2*)(smraw + O_WHP);
  __half*  H1  = (__half*) (smraw + O_H1);
  __half2* Qh  = (__half2*)(smraw + O_Q);
  __half2* W2h = (__half2*)(smraw + O_W2H);
  float*   sC  = (float*)  (smraw + O_C);
  float*   sS  = (float*)  (smraw + O_S);
  float*   sT  = (float*)  (smraw + O_T);
  float*   sE  = (float*)  (smraw + O_EMB);
  float*   sXM = (float*)  (smraw + O_XM);
  float*   sG1 = (float*)  (smraw + O_G1);
  float*   sY  = (float*)  (smraw + O_Y);
  float*   sPD = (float*)  (smraw + O_PD);

  const int tid  = threadIdx.x;
  const int w    = tid >> 5;
  const int lane = tid & 31;
  const int b    = blockIdx.x;
  const int base = w*16;

  // ---------------- stage 0: stage inputs / weights into SMEM ---------
  if (tid < 128) sC[tid] = gC[b*128 + tid];
  for (int i = tid; i < 1024; i += 256) sE[i] = gEmb[i];
  for (int i = tid; i < 2048; i += 256) {
    int k = i >> 5, l = i & 31;          // pack {W2[k][l], W2[k][l+32]}
    W2h[i] = __floats2half2_rn(__ldg(&gW2[k*64 + l]), __ldg(&gW2[k*64 + 32 + l]));
  }
  __syncthreads();

  // ------- stage 1: Wh1 = [c|emb] @ W1 (lane owns feats l, l+32) ------
  {
    float w1x[9], w1y[9];
    #pragma unroll
    for (int d = 0; d < 9; d++) {
      w1x[d] = __ldg(&gW1[d*64 + lane]);
      w1y[d] = __ldg(&gW1[d*64 + 32 + lane]);
    }
    const float aI0 = __ldg(&gA1[lane]),      aI1 = __ldg(&gA1[32 + lane]);
    const float aJ0 = __ldg(&gA1[64 + lane]), aJ1 = __ldg(&gA1[96 + lane]);
    #pragma unroll 2
    for (int r = 0; r < 16; r += 2) {
      const int n = base + r;
      float xr[2], yr[2];
      #pragma unroll
      for (int s = 0; s < 2; s++) {
        const int nn = n + s;
        const float c = sC[nn];
        float4 e0 = *(const float4*)&sE[nn*8];
        float4 e1 = *(const float4*)&sE[nn*8 + 4];
        float x = c*w1x[0] + e0.x*w1x[1] + e0.y*w1x[2] + e0.z*w1x[3] + e0.w*w1x[4]
                           + e1.x*w1x[5] + e1.y*w1x[6] + e1.z*w1x[7] + e1.w*w1x[8];
        float y = c*w1y[0] + e0.x*w1y[1] + e0.y*w1y[2] + e0.z*w1y[3] + e0.w*w1y[4]
                           + e1.x*w1y[5] + e1.y*w1y[6] + e1.z*w1y[7] + e1.w*w1y[8];
        xr[s] = x; yr[s] = y;
        float sp = wsum(x*aI0 + y*aI1);
        float tp = wsum(x*aJ0 + y*aJ1);
        if (lane == 0) { sS[nn] = sp; sT[nn] = tp; }
      }
      const int m = n >> 1;
      WHp[68*lane + m]        = __floats2half2_rn(xr[0], xr[1]);   // feat lane
      WHp[68*(lane+32) + m]   = __floats2half2_rn(yr[0], yr[1]);   // feat lane+32
    }
  }
  // MLP / gate hidden layers (depend only on c) — warps 0..3
  if (tid < 64) {
    float acc = gM1b[tid];
    #pragma unroll 4
    for (int n = 0; n < 128; n++) acc += sC[n] * __ldg(&gM1w[n*64 + tid]);
    sXM[tid] = fmaxf(acc, 0.f);
  } else if (tid < 128) {
    int h = tid - 64;
    float acc = gG1b[h];
    #pragma unroll 4
    for (int n = 0; n < 128; n++) acc += sC[n] * __ldg(&gG1w[n*64 + h]);
    sG1[h] = fmaxf(acc, 0.f);
  }
  __syncthreads();

  // MLP second layer (overlaps with GAT layer 1 on other warps)
  if (tid < 64) {
    float acc = gM2b[tid];
    #pragma unroll 8
    for (int k = 0; k < 64; k++) acc += sXM[k] * __ldg(&gM2w[k*64 + tid]);
    sY[tid] = fmaxf(acc, 0.f);
  }

  // ---------------- stage 3: GAT layer 1 (attn + agg + elu + LN) ------
  __half2* qw = Qh + (w << 9);                 // 512 half2 per warp
  const __half2* wp0 = WHp + 68*lane;          // feature lane
  const __half2* wp1 = WHp + 68*(lane + 32);   // feature lane+32
  #pragma unroll 1
  for (int g = 0; g < 2; g++) {
    const int base2 = base + g*8;
    const float4 tv4 = *(const float4*)&sT[4*lane];
    float uac[8];
    #pragma unroll 2
    for (int r = 0; r < 8; r++) {
      const int i = base2 + r;
      const float si = sS[i];
      float4 a4 = __ldg((const float4*)(gAdj + i*128 + 4*lane));
      float e0 = si + tv4.x; e0 = fmaxf(e0, 0.2f*e0);
      float e1 = si + tv4.y; e1 = fmaxf(e1, 0.2f*e1);
      float e2 = si + tv4.z; e2 = fmaxf(e2, 0.2f*e2);
      float e3 = si + tv4.w; e3 = fmaxf(e3, 0.2f*e3);
      float p0 = a4.x > 0.f ? __expf(e0) : 0.f;
      float p1 = a4.y > 0.f ? __expf(e1) : 0.f;
      float p2 = a4.z > 0.f ? __expf(e2) : 0.f;
      float p3 = a4.w > 0.f ? __expf(e3) : 0.f;
      float q0 = a4.x*p0, q1 = a4.y*p1, q2 = a4.z*p2, q3 = a4.w*p3;
      uac[r] = (q0+q1+q2+q3) + 1e-8f*(p0+p1+p2+p3);
      union { uint2 u; __half2 h[2]; } st;
      st.h[0] = __floats2half2_rn(q0, q1);
      st.h[1] = __floats2half2_rn(q2, q3);
      *(uint2*)&qw[r*64 + 2*lane] = st.u;
    }
    __syncwarp();
    __half2 a0[8], a1[8];
    #pragma unroll
    for (int r = 0; r < 8; r++) { a0[r] = __float2half2_rn(0.f); a1[r] = a0[r]; }
    #pragma unroll 2
    for (int mb = 0; mb < 16; mb++) {
      uint4 wv0 = *(const uint4*)(wp0 + mb*4);
      uint4 wv1 = *(const uint4*)(wp1 + mb*4);
      #pragma unroll
      for (int rb = 0; rb < 2; rb++) {
        uint4 q4[4];
        #pragma unroll
        for (int r4 = 0; r4 < 4; r4++)
          q4[r4] = *(const uint4*)&qw[(rb*4+r4)*64 + mb*4];
        #pragma unroll
        for (int u = 0; u < 4; u++) {
          __half2 w0u = ((const __half2*)&wv0)[u];
          __half2 w1u = ((const __half2*)&wv1)[u];
          #pragma unroll
          for (int r4 = 0; r4 < 4; r4++) {
            __half2 qq = ((const __half2*)&q4[r4])[u];
            a0[rb*4+r4] = __hfma2(qq, w0u, a0[rb*4+r4]);
            a1[rb*4+r4] = __hfma2(qq, w1u, a1[rb*4+r4]);
          }
        }
      }
    }
    // epilogue: scale + elu + LN1
    const float lg0 = __ldg(&gLn1g[lane]), lg1 = __ldg(&gLn1g[32 + lane]);
    const float lb0 = __ldg(&gLn1b[lane]), lb1 = __ldg(&gLn1b[32 + lane]);
    #pragma unroll
    for (int r = 0; r < 8; r++) {
      float scale = __fdividef(1.f, wsum(uac[r]));
      float2 f0 = __half22float2(a0[r]);
      float2 f1 = __half22float2(a1[r]);
      float v0 = (f0.x + f0.y)*scale, v1 = (f1.x + f1.y)*scale;
      v0 = v0 > 0.f ? v0 : __expf(v0) - 1.f;   // elu
      v1 = v1 > 0.f ? v1 : __expf(v1) - 1.f;
      float s1 = wsum(v0 + v1);
      float s2 = wsum(v0*v0 + v1*v1);
      float mu  = s1 * (1.f/64.f);
      float var = s2 * (1.f/64.f) - mu*mu;
      float inv = rsqrtf(var + 1e-5f);
      float d0 = v0 - mu, d1 = v1 - mu;
      H1[(base2+r)*64 + lane]      = __float2half_rn(d0*inv*lg0 + lb0);
      H1[(base2+r)*64 + 32 + lane] = __float2half_rn(d1*inv*lg1 + lb1);
    }
    __syncwarp();
  }
  __syncthreads();

  // ------- stage 4: Wh2 = h1 @ W2 (HFMA2, W2 from smem) + s2/t2 -------
  {
    const float aIx = __ldg(&gA2[lane]),      aIy = __ldg(&gA2[32 + lane]);
    const float aJx = __ldg(&gA2[64 + lane]), aJy = __ldg(&gA2[96 + lane]);
    #pragma unroll 1
    for (int g = 0; g < 2; g++) {
      const int base2 = base + g*8;
      __half2 acc[8];
      #pragma unroll
      for (int r = 0; r < 8; r++) acc[r] = __float2half2_rn(0.f);
      #pragma unroll 2
      for (int k4 = 0; k4 < 16; k4++) {
        __half2 wvh[4];
        #pragma unroll
        for (int u = 0; u < 4; u++)
          wvh[u] = W2h[(k4*4+u)*32 + lane];    // {W2[k][l], W2[k][l+32]}
        #pragma unroll
        for (int r = 0; r < 8; r++) {
          uint2 U = *(const uint2*)&H1[(base2+r)*64 + k4*4];   // broadcast
          __half2 h01 = ((const __half2*)&U)[0];
          __half2 h23 = ((const __half2*)&U)[1];
          acc[r] = __hfma2(__low2half2 (h01), wvh[0], acc[r]);
          acc[r] = __hfma2(__high2half2(h01), wvh[1], acc[r]);
          acc[r] = __hfma2(__low2half2 (h23), wvh[2], acc[r]);
          acc[r] = __hfma2(__high2half2(h23), wvh[3], acc[r]);
        }
      }
      // paired store into WHp + s/t epilogue   (acc = {feat l, feat l+32})
      #pragma unroll
      for (int r = 0; r < 8; r += 2) {
        const int m = (base2 + r) >> 1;
        WHp[68*lane + m]      = __lows2half2 (acc[r], acc[r+1]);
        WHp[68*(lane+32) + m] = __highs2half2(acc[r], acc[r+1]);
      }
      #pragma unroll
      for (int r = 0; r < 8; r++) {
        float2 axy = __half22float2(acc[r]);
        float sp = wsum(axy.x*aIx + axy.y*aIy);
        float tp = wsum(axy.x*aJx + axy.y*aJy);
        if (lane == 0) { sS[base2 + r] = sp; sT[base2 + r] = tp; }
      }
    }
  }
  __syncthreads();

  // ---------------- stage 6: GAT layer 2 + residual + LN + head -------
  float wpd = 0.f;
  #pragma unroll 1
  for (int g = 0; g < 2; g++) {
    const int base2 = base + g*8;
    const float4 tv4 = *(const float4*)&sT[4*lane];
    float uac[8];
    #pragma unroll 2
    for (int r = 0; r < 8; r++) {
      const int i = base2 + r;
      const float si = sS[i];
      float4 a4 = __ldg((const float4*)(gAdj + i*128 + 4*lane));
      float e0 = si + tv4.x; e0 = fmaxf(e0, 0.2f*e0);
      float e1 = si + tv4.y; e1 = fmaxf(e1, 0.2f*e1);
      float e2 = si + tv4.z; e2 = fmaxf(e2, 0.2f*e2);
      float e3 = si + tv4.w; e3 = fmaxf(e3, 0.2f*e3);
      float p0 = a4.x > 0.f ? __expf(e0) : 0.f;
      float p1 = a4.y > 0.f ? __expf(e1) : 0.f;
      float p2 = a4.z > 0.f ? __expf(e2) : 0.f;
      float p3 = a4.w > 0.f ? __expf(e3) : 0.f;
      float q0 = a4.x*p0, q1 = a4.y*p1, q2 = a4.z*p2, q3 = a4.w*p3;
      uac[r] = (q0+q1+q2+q3) + 1e-8f*(p0+p1+p2+p3);
      union { uint2 u; __half2 h[2]; } st;
      st.h[0] = __floats2half2_rn(q0, q1);
      st.h[1] = __floats2half2_rn(q2, q3);
      *(uint2*)&qw[r*64 + 2*lane] = st.u;
    }
    __syncwarp();
    __half2 a0[8], a1[8];
    #pragma unroll
    for (int r = 0; r < 8; r++) { a0[r] = __float2half2_rn(0.f); a1[r] = a0[r]; }
    #pragma unroll 2
    for (int mb = 0; mb < 16; mb++) {
      uint4 wv0 = *(const uint4*)(wp0 + mb*4);
      uint4 wv1 = *(const uint4*)(wp1 + mb*4);
      #pragma unroll
      for (int rb = 0; rb < 2; rb++) {
        uint4 q4[4];
        #pragma unroll
        for (int r4 = 0; r4 < 4; r4++)
          q4[r4] = *(const uint4*)&qw[(rb*4+r4)*64 + mb*4];
        #pragma unroll
        for (int u = 0; u < 4; u++) {
          __half2 w0u = ((const __half2*)&wv0)[u];
          __half2 w1u = ((const __half2*)&wv1)[u];
          #pragma unroll
          for (int r4 = 0; r4 < 4; r4++) {
            __half2 qq = ((const __half2*)&q4[r4])[u];
            a0[rb*4+r4] = __hfma2(qq, w0u, a0[rb*4+r4]);
            a1[rb*4+r4] = __hfma2(qq, w1u, a1[rb*4+r4]);
          }
        }
      }
    }
    // epilogue: scale + residual + relu + LN2 + head partial
    const float mg0 = __ldg(&gLn2g[lane]), mg1 = __ldg(&gLn2g[32 + lane]);
    const float mb0 = __ldg(&gLn2b[lane]), mb1 = __ldg(&gLn2b[32 + lane]);
    const float hg0 = __ldg(&gHgw[lane]),  hg1 = __ldg(&gHgw[32 + lane]);
    #pragma unroll
    for (int r = 0; r < 8; r++) {
      float scale = __fdividef(1.f, wsum(uac[r]));
      float2 f0 = __half22float2(a0[r]);
      float2 f1 = __half22float2(a1[r]);
      float h1x = __half2float(H1[(base2+r)*64 + lane]);
      float h1y = __half2float(H1[(base2+r)*64 + 32 + lane]);
      float v0 = fmaxf((f0.x + f0.y)*scale + h1x, 0.f);   // relu(h2 + h1)
      float v1 = fmaxf((f1.x + f1.y)*scale + h1y, 0.f);
      float s1 = wsum(v0 + v1);
      float s2 = wsum(v0*v0 + v1*v1);
      float mu  = s1 * (1.f/64.f);
      float var = s2 * (1.f/64.f) - mu*mu;
      float inv = rsqrtf(var + 1e-5f);
      float d0 = v0 - mu, d1 = v1 - mu;
      float y0 = d0*inv*mg0 + mb0;
      float y1 = d1*inv*mg1 + mb1;
      wpd += y0*hg0 + y1*hg1;              // defer cross-lane reduce
    }
    __syncwarp();
  }
  wpd = wsum(wpd);                          // one reduction for all 16 rows
  if (lane == 0) sPD[w] = wpd;
  __syncthreads();

  // ---------------- final combine (warp 0, deterministic) -------------
  if (w == 0) {
    float qm = sY[lane]*__ldg(&gHmw[lane])
             + sY[32 + lane]*__ldg(&gHmw[32 + lane]);
    float gp = sG1[lane]*__ldg(&gG2w[lane])
             + sG1[32 + lane]*__ldg(&gG2w[32 + lane]);
    float ac = (lane < 8) ? sPD[lane] : 0.f;
    qm = wsum(qm); gp = wsum(gp); ac = wsum(ac);
    if (lane == 0) {
      float qgat = ac * (1.f/128.f) + gHgb[0];
      float qmlp = qm + gHmb[0];
      float gv   = gp + gG2b[0];
      float gate = __fdividef(1.f, 1.f + __expf(-gv));
      gOut[b] = qmlp + gate * qgat;                    // GAT_SCALE = 1
    }
  }
}

extern "C" void kernel_launch(void* const* d_in, const int* in_sizes, int n_in,
                              void* d_out, int out_size) {
  (void)n_in; (void)out_size;
  const int B = in_sizes[0] / 128;
  cudaFuncSetAttribute(graphmixer_kernel,
                       cudaFuncAttributeMaxDynamicSharedMemorySize, SMEM_BYTES);
  graphmixer_kernel<<<B, 256, SMEM_BYTES>>>(
      (const float*)d_in[0],  (const float*)d_in[1],  (const float*)d_in[2],
      (const float*)d_in[3],  (const float*)d_in[4],  (const float*)d_in[5],
      (const float*)d_in[6],  (const float*)d_in[7],  (const float*)d_in[8],
      (const float*)d_in[9],  (const float*)d_in[10], (const float*)d_in[11],
      (const float*)d_in[12], (const float*)d_in[13], (const float*)d_in[14],
      (const float*)d_in[15], (const float*)d_in[16], (const float*)d_in[17],
      (const float*)d_in[18], (const float*)d_in[19], (const float*)d_in[20],
      (const float*)d_in[21], (const float*)d_in[22], (float*)d_out);
}

// round 16
// speedup vs baseline: 1.0036x; 1.0036x over previous
#include <cuda_runtime.h>
#include <cuda_fp16.h>

#define FULL 0xffffffffu

__device__ __forceinline__ float wsum(float v){
  #pragma unroll
  for (int o = 16; o; o >>= 1) v += __shfl_xor_sync(FULL, v, o);
  return v;
}

// ---- shared memory layout (byte offsets) ----
// WHp: feature-major paired nodes: plane f (0..63) at WHp + 68*f,
//      entry m (0..63) = {WH[2m][f], WH[2m+1][f]}.  68*4B = 272B per plane
//      -> every plane 16B-aligned; LDS.128 conflict-free (stride 68 % 32 == 4).
#define O_WHP  0        // 64 planes x 68 half2                     (17408 B)
#define O_H1   17408    // half 128x64 row-major                    (16384 B)
#define O_Q    33792    // half2 8 warps x 8 rows x 64 pairs        (16384 B)
#define O_W2H  50176    // half2 64x32 : {W2[k][l], W2[k][l+32]}    (8192 B)
#define O_C    58368    // float 128
#define O_S    58880    // float 128
#define O_T    59392    // float 128
#define O_EMB  59904    // float 128x8
#define O_XM   64000    // float 64
#define O_G1   64256    // float 64
#define O_Y    64512    // float 64
#define O_PD   64768    // float 8
#define SMEM_BYTES 64800

__global__ void __launch_bounds__(256, 3)
graphmixer_kernel(const float* __restrict__ gC,   const float* __restrict__ gAdj,
                  const float* __restrict__ gEmb, const float* __restrict__ gW1,
                  const float* __restrict__ gA1,  const float* __restrict__ gW2,
                  const float* __restrict__ gA2,  const float* __restrict__ gLn1g,
                  const float* __restrict__ gLn1b,const float* __restrict__ gLn2g,
                  const float* __restrict__ gLn2b,const float* __restrict__ gHgw,
                  const float* __restrict__ gHgb, const float* __restrict__ gM1w,
                  const float* __restrict__ gM1b, const float* __restrict__ gM2w,
                  const float* __restrict__ gM2b, const float* __restrict__ gHmw,
                  const float* __restrict__ gHmb, const float* __restrict__ gG1w,
                  const float* __restrict__ gG1b, const float* __restrict__ gG2w,
                  const float* __restrict__ gG2b, float* __restrict__ gOut)
{
  extern __shared__ char smraw[];
  __half2* WHp = (__half2*)(smraw + O_WHP);
  __half*  H1  = (__half*) (smraw + O_H1);
  __half2* Qh  = (__half2*)(smraw + O_Q);
  __half2* W2h = (__half2*)(smraw + O_W2H);
  float*   sC  = (float*)  (smraw + O_C);
  float*   sS  = (float*)  (smraw + O_S);
  float*   sT  = (float*)  (smraw + O_T);
  float*   sE  = (float*)  (smraw + O_EMB);
  float*   sXM = (float*)  (smraw + O_XM);
  float*   sG1 = (float*)  (smraw + O_G1);
  float*   sY  = (float*)  (smraw + O_Y);
  float*   sPD = (float*)  (smraw + O_PD);

  const int tid  = threadIdx.x;
  const int w    = tid >> 5;
  const int lane = tid & 31;
  const int b    = blockIdx.x;
  const int base = w*16;

  // ---------------- stage 0: stage inputs / weights into SMEM ---------
  if (tid < 128) sC[tid] = gC[b*128 + tid];
  for (int i = tid; i < 1024; i += 256) sE[i] = gEmb[i];
  for (int i = tid; i < 2048; i += 256) {
    int k = i >> 5, l = i & 31;          // pack {W2[k][l], W2[k][l+32]}
    W2h[i] = __floats2half2_rn(__ldg(&gW2[k*64 + l]), __ldg(&gW2[k*64 + 32 + l]));
  }
  __syncthreads();

  // ------- stage 1: Wh1 = [c|emb] @ W1 (lane owns feats l, l+32) ------
  {
    float w1x[9], w1y[9];
    #pragma unroll
    for (int d = 0; d < 9; d++) {
      w1x[d] = __ldg(&gW1[d*64 + lane]);
      w1y[d] = __ldg(&gW1[d*64 + 32 + lane]);
    }
    const float aI0 = __ldg(&gA1[lane]),      aI1 = __ldg(&gA1[32 + lane]);
    const float aJ0 = __ldg(&gA1[64 + lane]), aJ1 = __ldg(&gA1[96 + lane]);
    #pragma unroll 2
    for (int r = 0; r < 16; r += 2) {
      const int n = base + r;
      float xr[2], yr[2];
      #pragma unroll
      for (int s = 0; s < 2; s++) {
        const int nn = n + s;
        const float c = sC[nn];
        float4 e0 = *(const float4*)&sE[nn*8];
        float4 e1 = *(const float4*)&sE[nn*8 + 4];
        float x = c*w1x[0] + e0.x*w1x[1] + e0.y*w1x[2] + e0.z*w1x[3] + e0.w*w1x[4]
                           + e1.x*w1x[5] + e1.y*w1x[6] + e1.z*w1x[7] + e1.w*w1x[8];
        float y = c*w1y[0] + e0.x*w1y[1] + e0.y*w1y[2] + e0.z*w1y[3] + e0.w*w1y[4]
                           + e1.x*w1y[5] + e1.y*w1y[6] + e1.z*w1y[7] + e1.w*w1y[8];
        xr[s] = x; yr[s] = y;
        float sp = wsum(x*aI0 + y*aI1);
        float tp = wsum(x*aJ0 + y*aJ1);
        if (lane == 0) { sS[nn] = sp; sT[nn] = tp; }
      }
      const int m = n >> 1;
      WHp[68*lane + m]        = __floats2half2_rn(xr[0], xr[1]);   // feat lane
      WHp[68*(lane+32) + m]   = __floats2half2_rn(yr[0], yr[1]);   // feat lane+32
    }
  }
  // MLP / gate hidden layers (depend only on c) — warps 0..3
  if (tid < 64) {
    float acc = gM1b[tid];
    #pragma unroll 4
    for (int n = 0; n < 128; n++) acc += sC[n] * __ldg(&gM1w[n*64 + tid]);
    sXM[tid] = fmaxf(acc, 0.f);
  } else if (tid < 128) {
    int h = tid - 64;
    float acc = gG1b[h];
    #pragma unroll 4
    for (int n = 0; n < 128; n++) acc += sC[n] * __ldg(&gG1w[n*64 + h]);
    sG1[h] = fmaxf(acc, 0.f);
  }
  __syncthreads();

  // MLP second layer (overlaps with GAT layer 1 on other warps)
  if (tid < 64) {
    float acc = gM2b[tid];
    #pragma unroll 8
    for (int k = 0; k < 64; k++) acc += sXM[k] * __ldg(&gM2w[k*64 + tid]);
    sY[tid] = fmaxf(acc, 0.f);
  }

  // ---------------- stage 3: GAT layer 1 (attn + agg + elu + LN) ------
  __half2* qw = Qh + (w << 9);                 // 512 half2 per warp
  const __half2* wp0 = WHp + 68*lane;          // feature lane
  const __half2* wp1 = WHp + 68*(lane + 32);   // feature lane+32
  #pragma unroll 1
  for (int g = 0; g < 2; g++) {
    const int base2 = base + g*8;
    const float4 tv4 = *(const float4*)&sT[4*lane];
    float uac[8];
    #pragma unroll 2
    for (int r = 0; r < 8; r++) {
      const int i = base2 + r;
      const float si = sS[i];
      float4 a4 = __ldg((const float4*)(gAdj + i*128 + 4*lane));
      float e0 = si + tv4.x; e0 = fmaxf(e0, 0.2f*e0);
      float e1 = si + tv4.y; e1 = fmaxf(e1, 0.2f*e1);
      float e2 = si + tv4.z; e2 = fmaxf(e2, 0.2f*e2);
      float e3 = si + tv4.w; e3 = fmaxf(e3, 0.2f*e3);
      float p0 = a4.x > 0.f ? __expf(e0) : 0.f;
      float p1 = a4.y > 0.f ? __expf(e1) : 0.f;
      float p2 = a4.z > 0.f ? __expf(e2) : 0.f;
      float p3 = a4.w > 0.f ? __expf(e3) : 0.f;
      float q0 = a4.x*p0, q1 = a4.y*p1, q2 = a4.z*p2, q3 = a4.w*p3;
      uac[r] = (q0+q1+q2+q3) + 1e-8f*(p0+p1+p2+p3);
      union { uint2 u; __half2 h[2]; } st;
      st.h[0] = __floats2half2_rn(q0, q1);
      st.h[1] = __floats2half2_rn(q2, q3);
      *(uint2*)&qw[r*64 + 2*lane] = st.u;
    }
    __syncwarp();
    __half2 a0[8], a1[8];
    #pragma unroll
    for (int r = 0; r < 8; r++) { a0[r] = __float2half2_rn(0.f); a1[r] = a0[r]; }
    #pragma unroll 2
    for (int mb = 0; mb < 16; mb++) {
      uint4 wv0 = *(const uint4*)(wp0 + mb*4);
      uint4 wv1 = *(const uint4*)(wp1 + mb*4);
      #pragma unroll
      for (int rb = 0; rb < 2; rb++) {
        uint4 q4[4];
        #pragma unroll
        for (int r4 = 0; r4 < 4; r4++)
          q4[r4] = *(const uint4*)&qw[(rb*4+r4)*64 + mb*4];
        #pragma unroll
        for (int u = 0; u < 4; u++) {
          __half2 w0u = ((const __half2*)&wv0)[u];
          __half2 w1u = ((const __half2*)&wv1)[u];
          #pragma unroll
          for (int r4 = 0; r4 < 4; r4++) {
            __half2 qq = ((const __half2*)&q4[r4])[u];
            a0[rb*4+r4] = __hfma2(qq, w0u, a0[rb*4+r4]);
            a1[rb*4+r4] = __hfma2(qq, w1u, a1[rb*4+r4]);
          }
        }
      }
    }
    // epilogue: scale + elu + LN1
    const float lg0 = __ldg(&gLn1g[lane]), lg1 = __ldg(&gLn1g[32 + lane]);
    const float lb0 = __ldg(&gLn1b[lane]), lb1 = __ldg(&gLn1b[32 + lane]);
    #pragma unroll
    for (int r = 0; r < 8; r++) {
      float scale = __fdividef(1.f, wsum(uac[r]));
      float2 f0 = __half22float2(a0[r]);
      float2 f1 = __half22float2(a1[r]);
      float v0 = (f0.x + f0.y)*scale, v1 = (f1.x + f1.y)*scale;
      v0 = v0 > 0.f ? v0 : __expf(v0) - 1.f;   // elu
      v1 = v1 > 0.f ? v1 : __expf(v1) - 1.f;
      float s1 = wsum(v0 + v1);
      float s2 = wsum(v0*v0 + v1*v1);
      float mu  = s1 * (1.f/64.f);
      float var = s2 * (1.f/64.f) - mu*mu;
      float inv = rsqrtf(var + 1e-5f);
      float d0 = v0 - mu, d1 = v1 - mu;
      H1[(base2+r)*64 + lane]      = __float2half_rn(d0*inv*lg0 + lb0);
      H1[(base2+r)*64 + 32 + lane] = __float2half_rn(d1*inv*lg1 + lb1);
    }
    __syncwarp();
  }
  __syncthreads();

  // ------- stage 4: Wh2 = h1 @ W2 (HFMA2, W2 from smem) + s2/t2 -------
  {
    const float aIx = __ldg(&gA2[lane]),      aIy = __ldg(&gA2[32 + lane]);
    const float aJx = __ldg(&gA2[64 + lane]), aJy = __ldg(&gA2[96 + lane]);
    #pragma unroll 1
    for (int g = 0; g < 2; g++) {
      const int base2 = base + g*8;
      __half2 acc[8];
      #pragma unroll
      for (int r = 0; r < 8; r++) acc[r] = __float2half2_rn(0.f);
      #pragma unroll 2
      for (int k4 = 0; k4 < 16; k4++) {
        __half2 wvh[4];
        #pragma unroll
        for (int u = 0; u < 4; u++)
          wvh[u] = W2h[(k4*4+u)*32 + lane];    // {W2[k][l], W2[k][l+32]}
        #pragma unroll
        for (int r = 0; r < 8; r++) {
          uint2 U = *(const uint2*)&H1[(base2+r)*64 + k4*4];   // broadcast
          __half2 h01 = ((const __half2*)&U)[0];
          __half2 h23 = ((const __half2*)&U)[1];
          acc[r] = __hfma2(__low2half2 (h01), wvh[0], acc[r]);
          acc[r] = __hfma2(__high2half2(h01), wvh[1], acc[r]);
          acc[r] = __hfma2(__low2half2 (h23), wvh[2], acc[r]);
          acc[r] = __hfma2(__high2half2(h23), wvh[3], acc[r]);
        }
      }
      // paired store into WHp + s/t epilogue   (acc = {feat l, feat l+32})
      #pragma unroll
      for (int r = 0; r < 8; r += 2) {
        const int m = (base2 + r) >> 1;
        WHp[68*lane + m]      = __lows2half2 (acc[r], acc[r+1]);
        WHp[68*(lane+32) + m] = __highs2half2(acc[r], acc[r+1]);
      }
      #pragma unroll
      for (int r = 0; r < 8; r++) {
        float2 axy = __half22float2(acc[r]);
        float sp = wsum(axy.x*aIx + axy.y*aIy);
        float tp = wsum(axy.x*aJx + axy.y*aJy);
        if (lane == 0) { sS[base2 + r] = sp; sT[base2 + r] = tp; }
      }
    }
  }
  __syncthreads();

  // ---------------- stage 6: GAT layer 2 + residual + LN + head -------
  float wpd = 0.f;
  #pragma unroll 1
  for (int g = 0; g < 2; g++) {
    const int base2 = base + g*8;
    const float4 tv4 = *(const float4*)&sT[4*lane];
    float uac[8];
    #pragma unroll 2
    for (int r = 0; r < 8; r++) {
      const int i = base2 + r;
      const float si = sS[i];
      float4 a4 = __ldg((const float4*)(gAdj + i*128 + 4*lane));
      float e0 = si + tv4.x; e0 = fmaxf(e0, 0.2f*e0);
      float e1 = si + tv4.y; e1 = fmaxf(e1, 0.2f*e1);
      float e2 = si + tv4.z; e2 = fmaxf(e2, 0.2f*e2);
      float e3 = si + tv4.w; e3 = fmaxf(e3, 0.2f*e3);
      float p0 = a4.x > 0.f ? __expf(e0) : 0.f;
      float p1 = a4.y > 0.f ? __expf(e1) : 0.f;
      float p2 = a4.z > 0.f ? __expf(e2) : 0.f;
      float p3 = a4.w > 0.f ? __expf(e3) : 0.f;
      float q0 = a4.x*p0, q1 = a4.y*p1, q2 = a4.z*p2, q3 = a4.w*p3;
      uac[r] = (q0+q1+q2+q3) + 1e-8f*(p0+p1+p2+p3);
      union { uint2 u; __half2 h[2]; } st;
      st.h[0] = __floats2half2_rn(q0, q1);
      st.h[1] = __floats2half2_rn(q2, q3);
      *(uint2*)&qw[r*64 + 2*lane] = st.u;
    }
    __syncwarp();
    __half2 a0[8], a1[8];
    #pragma unroll
    for (int r = 0; r < 8; r++) { a0[r] = __float2half2_rn(0.f); a1[r] = a0[r]; }
    #pragma unroll 2
    for (int mb = 0; mb < 16; mb++) {
      uint4 wv0 = *(const uint4*)(wp0 + mb*4);
      uint4 wv1 = *(const uint4*)(wp1 + mb*4);
      #pragma unroll
      for (int rb = 0; rb < 2; rb++) {
        uint4 q4[4];
        #pragma unroll
        for (int r4 = 0; r4 < 4; r4++)
          q4[r4] = *(const uint4*)&qw[(rb*4+r4)*64 + mb*4];
        #pragma unroll
        for (int u = 0; u < 4; u++) {
          __half2 w0u = ((const __half2*)&wv0)[u];
          __half2 w1u = ((const __half2*)&wv1)[u];
          #pragma unroll
          for (int r4 = 0; r4 < 4; r4++) {
            __half2 qq = ((const __half2*)&q4[r4])[u];
            a0[rb*4+r4] = __hfma2(qq, w0u, a0[rb*4+r4]);
            a1[rb*4+r4] = __hfma2(qq, w1u, a1[rb*4+r4]);
          }
        }
      }
    }
    // epilogue: scale + residual + relu + LN2 + head partial
    const float mg0 = __ldg(&gLn2g[lane]), mg1 = __ldg(&gLn2g[32 + lane]);
    const float mb0 = __ldg(&gLn2b[lane]), mb1 = __ldg(&gLn2b[32 + lane]);
    const float hg0 = __ldg(&gHgw[lane]),  hg1 = __ldg(&gHgw[32 + lane]);
    #pragma unroll
    for (int r = 0; r < 8; r++) {
      float scale = __fdividef(1.f, wsum(uac[r]));
      float2 f0 = __half22float2(a0[r]);
      float2 f1 = __half22float2(a1[r]);
      float h1x = __half2float(H1[(base2+r)*64 + lane]);
      float h1y = __half2float(H1[(base2+r)*64 + 32 + lane]);
      float v0 = fmaxf((f0.x + f0.y)*scale + h1x, 0.f);   // relu(h2 + h1)
      float v1 = fmaxf((f1.x + f1.y)*scale + h1y, 0.f);
      float s1 = wsum(v0 + v1);
      float s2 = wsum(v0*v0 + v1*v1);
      float mu  = s1 * (1.f/64.f);
      float var = s2 * (1.f/64.f) - mu*mu;
      float inv = rsqrtf(var + 1e-5f);
      float d0 = v0 - mu, d1 = v1 - mu;
      float y0 = d0*inv*mg0 + mb0;
      float y1 = d1*inv*mg1 + mb1;
      wpd += y0*hg0 + y1*hg1;              // defer cross-lane reduce
    }
    __syncwarp();
  }
  wpd = wsum(wpd);                          // one reduction for all 16 rows
  if (lane == 0) sPD[w] = wpd;
  __syncthreads();

  // ---------------- final combine (warp 0, deterministic) -------------
  if (w == 0) {
    float qm = sY[lane]*__ldg(&gHmw[lane])
             + sY[32 + lane]*__ldg(&gHmw[32 + lane]);
    float gp = sG1[lane]*__ldg(&gG2w[lane])
             + sG1[32 + lane]*__ldg(&gG2w[32 + lane]);
    float ac = (lane < 8) ? sPD[lane] : 0.f;
    qm = wsum(qm); gp = wsum(gp); ac = wsum(ac);
    if (lane == 0) {
      float qgat = ac * (1.f/128.f) + gHgb[0];
      float qmlp = qm + gHmb[0];
      float gv   = gp + gG2b[0];
      float gate = __fdividef(1.f, 1.f + __expf(-gv));
      gOut[b] = qmlp + gate * qgat;                    // GAT_SCALE = 1
    }
  }
}

extern "C" void kernel_launch(void* const* d_in, const int* in_sizes, int n_in,
                              void* d_out, int out_size) {
  (void)n_in; (void)out_size;
  const int B = in_sizes[0] / 128;
  cudaFuncSetAttribute(graphmixer_kernel,
                       cudaFuncAttributeMaxDynamicSharedMemorySize, SMEM_BYTES);
  graphmixer_kernel<<<B, 256, SMEM_BYTES>>>(
      (const float*)d_in[0],  (const float*)d_in[1],  (const float*)d_in[2],
      (const float*)d_in[3],  (const float*)d_in[4],  (const float*)d_in[5],
      (const float*)d_in[6],  (const float*)d_in[7],  (const float*)d_in[8],
      (const float*)d_in[9],  (const float*)d_in[10], (const float*)d_in[11],
      (const float*)d_in[12], (const float*)d_in[13], (const float*)d_in[14],
      (const float*)d_in[15], (const float*)d_in[16], (const float*)d_in[17],
      (const float*)d_in[18], (const float*)d_in[19], (const float*)d_in[20],
      (const float*)d_in[21], (const float*)d_in[22], (float*)d_out);
}

// round 17
// speedup vs baseline: 1.0038x; 1.0002x over previous
#include <cuda_runtime.h>
#include <cuda_fp16.h>

#define FULL 0xffffffffu

__device__ __forceinline__ float wsum(float v){
  #pragma unroll
  for (int o = 16; o; o >>= 1) v += __shfl_xor_sync(FULL, v, o);
  return v;
}

// ---- shared memory layout (byte offsets) ----
// WHp: feature-major paired nodes: plane f (0..63) at WHp + 68*f,
//      entry m (0..63) = {WH[2m][f], WH[2m+1][f]}.  68*4B = 272B per plane
//      -> every plane 16B-aligned; LDS.128 conflict-free (stride 68 % 32 == 4).
#define O_WHP  0        // 64 planes x 68 half2                     (17408 B)
#define O_H1   17408    // half 128x64 row-major                    (16384 B)
#define O_Q    33792    // half2 8 warps x 8 rows x 64 pairs        (16384 B)
#define O_W2H  50176    // half2 64x32 : {W2[k][l], W2[k][l+32]}    (8192 B)
#define O_C    58368    // float 128
#define O_S    58880    // float 128
#define O_T    59392    // float 128
#define O_EMB  59904    // float 128x8
#define O_XM   64000    // float 64
#define O_G1   64256    // float 64
#define O_Y    64512    // float 64
#define O_PD   64768    // float 8
#define SMEM_BYTES 64800

__global__ void __launch_bounds__(256, 3)
graphmixer_kernel(const float* __restrict__ gC,   const float* __restrict__ gAdj,
                  const float* __restrict__ gEmb, const float* __restrict__ gW1,
                  const float* __restrict__ gA1,  const float* __restrict__ gW2,
                  const float* __restrict__ gA2,  const float* __restrict__ gLn1g,
                  const float* __restrict__ gLn1b,const float* __restrict__ gLn2g,
                  const float* __restrict__ gLn2b,const float* __restrict__ gHgw,
                  const float* __restrict__ gHgb, const float* __restrict__ gM1w,
                  const float* __restrict__ gM1b, const float* __restrict__ gM2w,
                  const float* __restrict__ gM2b, const float* __restrict__ gHmw,
                  const float* __restrict__ gHmb, const float* __restrict__ gG1w,
                  const float* __restrict__ gG1b, const float* __restrict__ gG2w,
                  const float* __restrict__ gG2b, float* __restrict__ gOut)
{
  extern __shared__ char smraw[];
  __half2* WHp = (__half2*)(smraw + O_WHP);
  __half*  H1  = (__half*) (smraw + O_H1);
  __half2* Qh  = (__half2*)(smraw + O_Q);
  __half2* W2h = (__half2*)(smraw + O_W2H);
  float*   sC  = (float*)  (smraw + O_C);
  float*   sS  = (float*)  (smraw + O_S);
  float*   sT  = (float*)  (smraw + O_T);
  float*   sE  = (float*)  (smraw + O_EMB);
  float*   sXM = (float*)  (smraw + O_XM);
  float*   sG1 = (float*)  (smraw + O_G1);
  float*   sY  = (float*)  (smraw + O_Y);
  float*   sPD = (float*)  (smraw + O_PD);

  const int tid  = threadIdx.x;
  const int w    = tid >> 5;
  const int lane = tid & 31;
  const int b    = blockIdx.x;
  const int base = w*16;

  // ---------------- stage 0: stage inputs / weights into SMEM ---------
  if (tid < 128) sC[tid] = gC[b*128 + tid];
  for (int i = tid; i < 1024; i += 256) sE[i] = gEmb[i];
  for (int i = tid; i < 2048; i += 256) {
    int k = i >> 5, l = i & 31;          // pack {W2[k][l], W2[k][l+32]}
    W2h[i] = __floats2half2_rn(__ldg(&gW2[k*64 + l]), __ldg(&gW2[k*64 + 32 + l]));
  }
  __syncthreads();

  // ------- stage 1: Wh1 = [c|emb] @ W1 (lane owns feats l, l+32) ------
  {
    float w1x[9], w1y[9];
    #pragma unroll
    for (int d = 0; d < 9; d++) {
      w1x[d] = __ldg(&gW1[d*64 + lane]);
      w1y[d] = __ldg(&gW1[d*64 + 32 + lane]);
    }
    const float aI0 = __ldg(&gA1[lane]),      aI1 = __ldg(&gA1[32 + lane]);
    const float aJ0 = __ldg(&gA1[64 + lane]), aJ1 = __ldg(&gA1[96 + lane]);
    #pragma unroll 2
    for (int r = 0; r < 16; r += 2) {
      const int n = base + r;
      float xr[2], yr[2];
      #pragma unroll
      for (int s = 0; s < 2; s++) {
        const int nn = n + s;
        const float c = sC[nn];
        float4 e0 = *(const float4*)&sE[nn*8];
        float4 e1 = *(const float4*)&sE[nn*8 + 4];
        float x = c*w1x[0] + e0.x*w1x[1] + e0.y*w1x[2] + e0.z*w1x[3] + e0.w*w1x[4]
                           + e1.x*w1x[5] + e1.y*w1x[6] + e1.z*w1x[7] + e1.w*w1x[8];
        float y = c*w1y[0] + e0.x*w1y[1] + e0.y*w1y[2] + e0.z*w1y[3] + e0.w*w1y[4]
                           + e1.x*w1y[5] + e1.y*w1y[6] + e1.z*w1y[7] + e1.w*w1y[8];
        xr[s] = x; yr[s] = y;
        float sp = wsum(x*aI0 + y*aI1);
        float tp = wsum(x*aJ0 + y*aJ1);
        if (lane == 0) { sS[nn] = sp; sT[nn] = tp; }
      }
      const int m = n >> 1;
      WHp[68*lane + m]        = __floats2half2_rn(xr[0], xr[1]);   // feat lane
      WHp[68*(lane+32) + m]   = __floats2half2_rn(yr[0], yr[1]);   // feat lane+32
    }
  }
  // MLP / gate hidden layers (depend only on c) — warps 0..3
  if (tid < 64) {
    float acc = gM1b[tid];
    #pragma unroll 4
    for (int n = 0; n < 128; n++) acc += sC[n] * __ldg(&gM1w[n*64 + tid]);
    sXM[tid] = fmaxf(acc, 0.f);
  } else if (tid < 128) {
    int h = tid - 64;
    float acc = gG1b[h];
    #pragma unroll 4
    for (int n = 0; n < 128; n++) acc += sC[n] * __ldg(&gG1w[n*64 + h]);
    sG1[h] = fmaxf(acc, 0.f);
  }
  __syncthreads();

  // MLP second layer (overlaps with GAT layer 1 on other warps)
  if (tid < 64) {
    float acc = gM2b[tid];
    #pragma unroll 8
    for (int k = 0; k < 64; k++) acc += sXM[k] * __ldg(&gM2w[k*64 + tid]);
    sY[tid] = fmaxf(acc, 0.f);
  }

  // ---------------- stage 3: GAT layer 1 (attn + agg + elu + LN) ------
  __half2* qw = Qh + (w << 9);                 // 512 half2 per warp
  const __half2* wp0 = WHp + 68*lane;          // feature lane
  const __half2* wp1 = WHp + 68*(lane + 32);   // feature lane+32
  #pragma unroll 1
  for (int g = 0; g < 2; g++) {
    const int base2 = base + g*8;
    const float4 tv4 = *(const float4*)&sT[4*lane];
    float uac[8];
    #pragma unroll 2
    for (int r = 0; r < 8; r++) {
      const int i = base2 + r;
      const float si = sS[i];
      float4 a4 = __ldg((const float4*)(gAdj + i*128 + 4*lane));
      float e0 = si + tv4.x; e0 = fmaxf(e0, 0.2f*e0);
      float e1 = si + tv4.y; e1 = fmaxf(e1, 0.2f*e1);
      float e2 = si + tv4.z; e2 = fmaxf(e2, 0.2f*e2);
      float e3 = si + tv4.w; e3 = fmaxf(e3, 0.2f*e3);
      float p0 = a4.x > 0.f ? __expf(e0) : 0.f;
      float p1 = a4.y > 0.f ? __expf(e1) : 0.f;
      float p2 = a4.z > 0.f ? __expf(e2) : 0.f;
      float p3 = a4.w > 0.f ? __expf(e3) : 0.f;
      float q0 = a4.x*p0, q1 = a4.y*p1, q2 = a4.z*p2, q3 = a4.w*p3;
      uac[r] = (q0+q1+q2+q3) + 1e-8f*(p0+p1+p2+p3);
      union { uint2 u; __half2 h[2]; } st;
      st.h[0] = __floats2half2_rn(q0, q1);
      st.h[1] = __floats2half2_rn(q2, q3);
      *(uint2*)&qw[r*64 + 2*lane] = st.u;
    }
    __syncwarp();
    __half2 a0[8], a1[8];
    #pragma unroll
    for (int r = 0; r < 8; r++) { a0[r] = __float2half2_rn(0.f); a1[r] = a0[r]; }
    #pragma unroll 2
    for (int mb = 0; mb < 16; mb++) {
      uint4 wv0 = *(const uint4*)(wp0 + mb*4);
      uint4 wv1 = *(const uint4*)(wp1 + mb*4);
      #pragma unroll
      for (int rb = 0; rb < 2; rb++) {
        uint4 q4[4];
        #pragma unroll
        for (int r4 = 0; r4 < 4; r4++)
          q4[r4] = *(const uint4*)&qw[(rb*4+r4)*64 + mb*4];
        #pragma unroll
        for (int u = 0; u < 4; u++) {
          __half2 w0u = ((const __half2*)&wv0)[u];
          __half2 w1u = ((const __half2*)&wv1)[u];
          #pragma unroll
          for (int r4 = 0; r4 < 4; r4++) {
            __half2 qq = ((const __half2*)&q4[r4])[u];
            a0[rb*4+r4] = __hfma2(qq, w0u, a0[rb*4+r4]);
            a1[rb*4+r4] = __hfma2(qq, w1u, a1[rb*4+r4]);
          }
        }
      }
    }
    // epilogue: scale + elu + LN1
    const float lg0 = __ldg(&gLn1g[lane]), lg1 = __ldg(&gLn1g[32 + lane]);
    const float lb0 = __ldg(&gLn1b[lane]), lb1 = __ldg(&gLn1b[32 + lane]);
    #pragma unroll
    for (int r = 0; r < 8; r++) {
      float scale = __fdividef(1.f, wsum(uac[r]));
      float2 f0 = __half22float2(a0[r]);
      float2 f1 = __half22float2(a1[r]);
      float v0 = (f0.x + f0.y)*scale, v1 = (f1.x + f1.y)*scale;
      v0 = v0 > 0.f ? v0 : __expf(v0) - 1.f;   // elu
      v1 = v1 > 0.f ? v1 : __expf(v1) - 1.f;
      float s1 = wsum(v0 + v1);
      float s2 = wsum(v0*v0 + v1*v1);
      float mu  = s1 * (1.f/64.f);
      float var = s2 * (1.f/64.f) - mu*mu;
      float inv = rsqrtf(var + 1e-5f);
      float d0 = v0 - mu, d1 = v1 - mu;
      H1[(base2+r)*64 + lane]      = __float2half_rn(d0*inv*lg0 + lb0);
      H1[(base2+r)*64 + 32 + lane] = __float2half_rn(d1*inv*lg1 + lb1);
    }
    __syncwarp();
  }
  __syncthreads();

  // ------- stage 4: Wh2 = h1 @ W2 (HFMA2, W2 from smem) + s2/t2 -------
  {
    const float aIx = __ldg(&gA2[lane]),      aIy = __ldg(&gA2[32 + lane]);
    const float aJx = __ldg(&gA2[64 + lane]), aJy = __ldg(&gA2[96 + lane]);
    #pragma unroll 1
    for (int g = 0; g < 2; g++) {
      const int base2 = base + g*8;
      __half2 acc[8];
      #pragma unroll
      for (int r = 0; r < 8; r++) acc[r] = __float2half2_rn(0.f);
      #pragma unroll 2
      for (int k4 = 0; k4 < 16; k4++) {
        __half2 wvh[4];
        #pragma unroll
        for (int u = 0; u < 4; u++)
          wvh[u] = W2h[(k4*4+u)*32 + lane];    // {W2[k][l], W2[k][l+32]}
        #pragma unroll
        for (int r = 0; r < 8; r++) {
          uint2 U = *(const uint2*)&H1[(base2+r)*64 + k4*4];   // broadcast
          __half2 h01 = ((const __half2*)&U)[0];
          __half2 h23 = ((const __half2*)&U)[1];
          acc[r] = __hfma2(__low2half2 (h01), wvh[0], acc[r]);
          acc[r] = __hfma2(__high2half2(h01), wvh[1], acc[r]);
          acc[r] = __hfma2(__low2half2 (h23), wvh[2], acc[r]);
          acc[r] = __hfma2(__high2half2(h23), wvh[3], acc[r]);
        }
      }
      // paired store into WHp + s/t epilogue   (acc = {feat l, feat l+32})
      #pragma unroll
      for (int r = 0; r < 8; r += 2) {
        const int m = (base2 + r) >> 1;
        WHp[68*lane + m]      = __lows2half2 (acc[r], acc[r+1]);
        WHp[68*(lane+32) + m] = __highs2half2(acc[r], acc[r+1]);
      }
      #pragma unroll
      for (int r = 0; r < 8; r++) {
        float2 axy = __half22float2(acc[r]);
        float sp = wsum(axy.x*aIx + axy.y*aIy);
        float tp = wsum(axy.x*aJx + axy.y*aJy);
        if (lane == 0) { sS[base2 + r] = sp; sT[base2 + r] = tp; }
      }
    }
  }
  __syncthreads();

  // ---------------- stage 6: GAT layer 2 + residual + LN + head -------
  float wpd = 0.f;
  #pragma unroll 1
  for (int g = 0; g < 2; g++) {
    const int base2 = base + g*8;
    const float4 tv4 = *(const float4*)&sT[4*lane];
    float uac[8];
    #pragma unroll 2
    for (int r = 0; r < 8; r++) {
      const int i = base2 + r;
      const float si = sS[i];
      float4 a4 = __ldg((const float4*)(gAdj + i*128 + 4*lane));
      float e0 = si + tv4.x; e0 = fmaxf(e0, 0.2f*e0);
      float e1 = si + tv4.y; e1 = fmaxf(e1, 0.2f*e1);
      float e2 = si + tv4.z; e2 = fmaxf(e2, 0.2f*e2);
      float e3 = si + tv4.w; e3 = fmaxf(e3, 0.2f*e3);
      float p0 = a4.x > 0.f ? __expf(e0) : 0.f;
      float p1 = a4.y > 0.f ? __expf(e1) : 0.f;
      float p2 = a4.z > 0.f ? __expf(e2) : 0.f;
      float p3 = a4.w > 0.f ? __expf(e3) : 0.f;
      float q0 = a4.x*p0, q1 = a4.y*p1, q2 = a4.z*p2, q3 = a4.w*p3;
      uac[r] = (q0+q1+q2+q3) + 1e-8f*(p0+p1+p2+p3);
      union { uint2 u; __half2 h[2]; } st;
      st.h[0] = __floats2half2_rn(q0, q1);
      st.h[1] = __floats2half2_rn(q2, q3);
      *(uint2*)&qw[r*64 + 2*lane] = st.u;
    }
    __syncwarp();
    __half2 a0[8], a1[8];
    #pragma unroll
    for (int r = 0; r < 8; r++) { a0[r] = __float2half2_rn(0.f); a1[r] = a0[r]; }
    #pragma unroll 2
    for (int mb = 0; mb < 16; mb++) {
      uint4 wv0 = *(const uint4*)(wp0 + mb*4);
      uint4 wv1 = *(const uint4*)(wp1 + mb*4);
      #pragma unroll
      for (int rb = 0; rb < 2; rb++) {
        uint4 q4[4];
        #pragma unroll
        for (int r4 = 0; r4 < 4; r4++)
          q4[r4] = *(const uint4*)&qw[(rb*4+r4)*64 + mb*4];
        #pragma unroll
        for (int u = 0; u < 4; u++) {
          __half2 w0u = ((const __half2*)&wv0)[u];
          __half2 w1u = ((const __half2*)&wv1)[u];
          #pragma unroll
          for (int r4 = 0; r4 < 4; r4++) {
            __half2 qq = ((const __half2*)&q4[r4])[u];
            a0[rb*4+r4] = __hfma2(qq, w0u, a0[rb*4+r4]);
            a1[rb*4+r4] = __hfma2(qq, w1u, a1[rb*4+r4]);
          }
        }
      }
    }
    // epilogue: scale + residual + relu + LN2 + head partial
    const float mg0 = __ldg(&gLn2g[lane]), mg1 = __ldg(&gLn2g[32 + lane]);
    const float mb0 = __ldg(&gLn2b[lane]), mb1 = __ldg(&gLn2b[32 + lane]);
    const float hg0 = __ldg(&gHgw[lane]),  hg1 = __ldg(&gHgw[32 + lane]);
    #pragma unroll
    for (int r = 0; r < 8; r++) {
      float scale = __fdividef(1.f, wsum(uac[r]));
      float2 f0 = __half22float2(a0[r]);
      float2 f1 = __half22float2(a1[r]);
      float h1x = __half2float(H1[(base2+r)*64 + lane]);
      float h1y = __half2float(H1[(base2+r)*64 + 32 + lane]);
      float v0 = fmaxf((f0.x + f0.y)*scale + h1x, 0.f);   // relu(h2 + h1)
      float v1 = fmaxf((f1.x + f1.y)*scale + h1y, 0.f);
      float s1 = wsum(v0 + v1);
      float s2 = wsum(v0*v0 + v1*v1);
      float mu  = s1 * (1.f/64.f);
      float var = s2 * (1.f/64.f) - mu*mu;
      float inv = rsqrtf(var + 1e-5f);
      float d0 = v0 - mu, d1 = v1 - mu;
      float y0 = d0*inv*mg0 + mb0;
      float y1 = d1*inv*mg1 + mb1;
      wpd += y0*hg0 + y1*hg1;              // defer cross-lane reduce
    }
    __syncwarp();
  }
  wpd = wsum(wpd);                          // one reduction for all 16 rows
  if (lane == 0) sPD[w] = wpd;
  __syncthreads();

  // ---------------- final combine (warp 0, deterministic) -------------
  if (w == 0) {
    float qm = sY[lane]*__ldg(&gHmw[lane])
             + sY[32 + lane]*__ldg(&gHmw[32 + lane]);
    float gp = sG1[lane]*__ldg(&gG2w[lane])
             + sG1[32 + lane]*__ldg(&gG2w[32 + lane]);
    float ac = (lane < 8) ? sPD[lane] : 0.f;
    qm = wsum(qm); gp = wsum(gp); ac = wsum(ac);
    if (lane == 0) {
      float qgat = ac * (1.f/128.f) + gHgb[0];
      float qmlp = qm + gHmb[0];
      float gv   = gp + gG2b[0];
      float gate = __fdividef(1.f, 1.f + __expf(-gv));
      gOut[b] = qmlp + gate * qgat;                    // GAT_SCALE = 1
    }
  }
}

extern "C" void kernel_launch(void* const* d_in, const int* in_sizes, int n_in,
                              void* d_out, int out_size) {
  (void)n_in; (void)out_size;
  const int B = in_sizes[0] / 128;
  cudaFuncSetAttribute(graphmixer_kernel,
                       cudaFuncAttributeMaxDynamicSharedMemorySize, SMEM_BYTES);
  graphmixer_kernel<<<B, 256, SMEM_BYTES>>>(
      (const float*)d_in[0],  (const float*)d_in[1],  (const float*)d_in[2],
      (const float*)d_in[3],  (const float*)d_in[4],  (const float*)d_in[5],
      (const float*)d_in[6],  (const float*)d_in[7],  (const float*)d_in[8],
      (const float*)d_in[9],  (const float*)d_in[10], (const float*)d_in[11],
      (const float*)d_in[12], (const float*)d_in[13], (const float*)d_in[14],
      (const float*)d_in[15], (const float*)d_in[16], (const float*)d_in[17],
      (const float*)d_in[18], (const float*)d_in[19], (const float*)d_in[20],
      (const float*)d_in[21], (const float*)d_in[22], (float*)d_out);
}